// round 2
// baseline (speedup 1.0000x reference)
#include <cuda_runtime.h>

// Problem constants (fixed by the dataset)
#define BATCH 32
#define HW    196      // 14*14 spatial positions
#define C     512      // input channels
#define D     8192     // sketch / output dimension
#define KT    14       // K-chunk for shared tiles (196 = 14*14)

typedef unsigned long long ull;

// Packed fp32x2 FMA (Blackwell): acc = a2 * b2 + acc  (2 independent FMAs)
#define FMA2(acc, a2, b2) \
    asm("fma.rn.f32x2 %0, %1, %2, %0;" : "+l"(acc) : "l"(a2), "l"(b2))

#define PACK2(out, lo, hi) \
    asm("mov.b64 %0, {%1, %2};" : "=l"(out) : "f"(lo), "f"(hi))

#define UNPACK2(lo, hi, in) \
    asm("mov.b64 {%0, %1}, %2;" : "=f"(lo), "=f"(hi) : "l"(in))

// Fused kernel:
//   grid (4, 4, 32): blockIdx.x = c1 chunk (128), blockIdx.y = c2 chunk (128),
//   blockIdx.z = batch. 256 threads, 8x8 accumulators per thread (packed as
//   8 x 4 fp32x2 over the c2 direction).
// Computes the 128x128 tile of M[b] = X1[b]^T X2[b] (K = 196) with the +/-1
// signs folded into the shared tiles, then scatters each product directly to
// gmem via RED.ADD at bucket (h1[c1]+h2[c2]) & 8191. No smem accumulator:
// keeps the shared-memory port free for the GEMM's LDS traffic; the REDs
// ride the LSU/L2 path and overlap the FMA work.
__global__ __launch_bounds__(256, 2)
void cbp_fused(const float* __restrict__ x1, const float* __restrict__ x2,
               const float* __restrict__ s1, const float* __restrict__ s2,
               const int*   __restrict__ h1, const int*   __restrict__ h2,
               float* __restrict__ out)
{
    __shared__ float X1s[KT][128];
    __shared__ float X2s[KT][128];

    const int tid = threadIdx.x;
    const int tx  = tid & 15;            // c2 direction
    const int ty  = tid >> 4;            // c1 direction
    const int b   = blockIdx.z;
    const int c1_base = blockIdx.x * 128;
    const int c2_base = blockIdx.y * 128;

    const float* X1 = x1 + (size_t)b * HW * C;
    const float* X2 = x2 + (size_t)b * HW * C;

    // Tile-load mapping: col = tid & 127 is constant per thread, so the
    // sign multiplier is loaded once.
    const int   lc  = tid & 127;
    const float s1l = __ldg(&s1[c1_base + lc]);
    const float s2l = __ldg(&s2[c2_base + lc]);

    // 8 rows x 4 packed-column-pairs of fp32x2 accumulators (= 8x8 scalars)
    ull accp[8][4];
    #pragma unroll
    for (int i = 0; i < 8; i++)
        #pragma unroll
        for (int j = 0; j < 4; j++) accp[i][j] = 0ULL;

    for (int k0 = 0; k0 < HW; k0 += KT) {
        __syncthreads();   // protect tiles from previous iteration's readers
        #pragma unroll
        for (int n = 0; n < (KT * 128) / 256; ++n) {   // 7 loads per tensor
            int idx = tid + n * 256;
            int kk  = idx >> 7;
            X1s[kk][lc] = X1[(k0 + kk) * C + c1_base + lc] * s1l;
            X2s[kk][lc] = X2[(k0 + kk) * C + c2_base + lc] * s2l;
        }
        __syncthreads();

        #pragma unroll
        for (int kk = 0; kk < KT; ++kk) {
            // a fragment: 8 c1 rows (broadcast within half-warp groups)
            float4 a0 = *(const float4*)&X1s[kk][ty * 4];
            float4 a1 = *(const float4*)&X1s[kk][64 + ty * 4];
            // b fragment: 8 c2 cols, contiguous pairs -> free fp32x2 packing
            float4 b0 = *(const float4*)&X2s[kk][tx * 4];
            float4 b1 = *(const float4*)&X2s[kk][64 + tx * 4];

            ull bv2[4];
            PACK2(bv2[0], b0.x, b0.y);
            PACK2(bv2[1], b0.z, b0.w);
            PACK2(bv2[2], b1.x, b1.y);
            PACK2(bv2[3], b1.z, b1.w);

            float av[8] = {a0.x, a0.y, a0.z, a0.w, a1.x, a1.y, a1.z, a1.w};
            #pragma unroll
            for (int i = 0; i < 8; i++) {
                ull a2;
                PACK2(a2, av[i], av[i]);   // duplicate into both halves
                #pragma unroll
                for (int j = 0; j < 4; j++)
                    FMA2(accp[i][j], a2, bv2[j]);
            }
        }
    }

    // ---- scatter directly to gmem via RED.ADD (no smem accumulator) ----
    int h1v[8], h2v[8];
    #pragma unroll
    for (int i = 0; i < 8; i++) {
        int c1 = c1_base + ((i < 4) ? (ty * 4 + i) : (64 + ty * 4 + i - 4));
        h1v[i] = __ldg(&h1[c1]);
    }
    #pragma unroll
    for (int j = 0; j < 8; j++) {
        int c2 = c2_base + ((j < 4) ? (tx * 4 + j) : (64 + tx * 4 + j - 4));
        h2v[j] = __ldg(&h2[c2]);
    }

    float* outb = out + (size_t)b * D;
    #pragma unroll
    for (int i = 0; i < 8; i++) {
        #pragma unroll
        for (int j2 = 0; j2 < 4; j2++) {
            float vlo, vhi;
            UNPACK2(vlo, vhi, accp[i][j2]);
            int jlo = 2 * j2;
            int jhi = 2 * j2 + 1;
            int dlo = (h1v[i] + h2v[jlo]) & (D - 1);
            int dhi = (h1v[i] + h2v[jhi]) & (D - 1);
            atomicAdd(&outb[dlo], vlo);   // result unused -> RED.E.ADD.F32
            atomicAdd(&outb[dhi], vhi);
        }
    }
}

__global__ void zero_out_kernel(float* __restrict__ out, int n)
{
    int i = blockIdx.x * blockDim.x + threadIdx.x;
    if (i < n) out[i] = 0.0f;
}

extern "C" void kernel_launch(void* const* d_in, const int* in_sizes, int n_in,
                              void* d_out, int out_size)
{
    const float* x1 = (const float*)d_in[0];   // bottom1 [32,14,14,512]
    const float* x2 = (const float*)d_in[1];   // bottom2 [32,14,14,512]
    const float* s1 = (const float*)d_in[2];   // rand_s_1 [512]
    const float* s2 = (const float*)d_in[3];   // rand_s_2 [512]
    const int*   h1 = (const int*)d_in[4];     // rand_h_1 [512]
    const int*   h2 = (const int*)d_in[5];     // rand_h_2 [512]
    float* out = (float*)d_out;                // [32, 8192] float32

    const int n = BATCH * D;
    zero_out_kernel<<<(n + 255) / 256, 256>>>(out, n);

    dim3 grid(4, 4, BATCH);   // 512 blocks
    cbp_fused<<<grid, 256>>>(x1, x2, s1, s2, h1, h2, out);
}

// round 4
// speedup vs baseline: 1.3003x; 1.3003x over previous
#include <cuda_runtime.h>

// Problem constants (fixed by the dataset)
#define BATCH 32
#define HW    196      // 14*14 spatial positions
#define C     512      // input channels
#define D     8192     // sketch / output dimension
#define KT    14       // K-chunk for shared tiles (196 = 14*14)

typedef unsigned long long ull;

// Packed fp32x2 FMA (Blackwell): acc = a2 * b2 + acc  (2 independent FMAs)
#define FMA2(acc, a2, b2) \
    asm("fma.rn.f32x2 %0, %1, %2, %0;" : "+l"(acc) : "l"(a2), "l"(b2))

#define PACK2(out, lo, hi) \
    asm("mov.b64 %0, {%1, %2};" : "=l"(out) : "f"(lo), "f"(hi))

#define UNPACK2(lo, hi, in) \
    asm("mov.b64 {%0, %1}, %2;" : "=f"(lo), "=f"(hi) : "l"(in))

// Fused kernel:
//   grid (4, 4, 32): blockIdx.x = c1 chunk (128), blockIdx.y = c2 chunk (128),
//   blockIdx.z = batch. 256 threads, 8x8 scalar accumulators per thread,
//   packed as 8 x 4 fp32x2 over the c2 direction (FFMA2 = 2x math rate).
// Computes the 128x128 tile of M[b] = X1[b]^T X2[b] (K = 196) with the +/-1
// signs folded into the shared tiles, scatters each product into a
// block-private smem copy of out[b,:] at bucket (h1[c1]+h2[c2]) & 8191
// (smem atomics overlap under the FMA work), then atomically flushes the
// private accumulator to gmem.
__global__ __launch_bounds__(256, 2)
void cbp_fused(const float* __restrict__ x1, const float* __restrict__ x2,
               const float* __restrict__ s1, const float* __restrict__ s2,
               const int*   __restrict__ h1, const int*   __restrict__ h2,
               float* __restrict__ out)
{
    __shared__ float X1s[KT][128];
    __shared__ float X2s[KT][128];
    __shared__ float outacc[D];          // 32 KB block-private accumulator

    const int tid = threadIdx.x;
    const int tx  = tid & 15;            // c2 direction
    const int ty  = tid >> 4;            // c1 direction
    const int b   = blockIdx.z;
    const int c1_base = blockIdx.x * 128;
    const int c2_base = blockIdx.y * 128;

    // zero private accumulator
    #pragma unroll
    for (int i = tid; i < D; i += 256) outacc[i] = 0.0f;

    const float* X1 = x1 + (size_t)b * HW * C;
    const float* X2 = x2 + (size_t)b * HW * C;

    // Tile-load mapping: col = tid & 127 is constant per thread, so the
    // sign multiplier is loaded once.
    const int   lc  = tid & 127;
    const float s1l = __ldg(&s1[c1_base + lc]);
    const float s2l = __ldg(&s2[c2_base + lc]);

    // 8 rows x 4 packed-column-pairs of fp32x2 accumulators (= 8x8 scalars)
    ull accp[8][4];
    #pragma unroll
    for (int i = 0; i < 8; i++)
        #pragma unroll
        for (int j = 0; j < 4; j++) accp[i][j] = 0ULL;

    for (int k0 = 0; k0 < HW; k0 += KT) {
        __syncthreads();   // protect tiles from previous iteration's readers
        #pragma unroll
        for (int n = 0; n < (KT * 128) / 256; ++n) {   // 7 loads per tensor
            int idx = tid + n * 256;
            int kk  = idx >> 7;
            X1s[kk][lc] = X1[(k0 + kk) * C + c1_base + lc] * s1l;
            X2s[kk][lc] = X2[(k0 + kk) * C + c2_base + lc] * s2l;
        }
        __syncthreads();

        #pragma unroll
        for (int kk = 0; kk < KT; ++kk) {
            // a fragment: 8 c1 rows (broadcast within half-warp groups)
            float4 a0 = *(const float4*)&X1s[kk][ty * 4];
            float4 a1 = *(const float4*)&X1s[kk][64 + ty * 4];
            // b fragment: 8 c2 cols, contiguous pairs -> free fp32x2 packing
            float4 b0 = *(const float4*)&X2s[kk][tx * 4];
            float4 b1 = *(const float4*)&X2s[kk][64 + tx * 4];

            ull bv2[4];
            PACK2(bv2[0], b0.x, b0.y);
            PACK2(bv2[1], b0.z, b0.w);
            PACK2(bv2[2], b1.x, b1.y);
            PACK2(bv2[3], b1.z, b1.w);

            float av[8] = {a0.x, a0.y, a0.z, a0.w, a1.x, a1.y, a1.z, a1.w};
            #pragma unroll
            for (int i = 0; i < 8; i++) {
                ull a2;
                PACK2(a2, av[i], av[i]);   // duplicate into both halves
                #pragma unroll
                for (int j = 0; j < 4; j++)
                    FMA2(accp[i][j], a2, bv2[j]);
            }
        }
    }

    // ---- scatter into the block-private smem accumulator ----
    int h1v[8], h2v[8];
    #pragma unroll
    for (int i = 0; i < 8; i++) {
        int c1 = c1_base + ((i < 4) ? (ty * 4 + i) : (64 + ty * 4 + i - 4));
        h1v[i] = __ldg(&h1[c1]);
    }
    #pragma unroll
    for (int j = 0; j < 8; j++) {
        int c2 = c2_base + ((j < 4) ? (tx * 4 + j) : (64 + tx * 4 + j - 4));
        h2v[j] = __ldg(&h2[c2]);
    }

    #pragma unroll
    for (int i = 0; i < 8; i++) {
        #pragma unroll
        for (int j2 = 0; j2 < 4; j2++) {
            float vlo, vhi;
            UNPACK2(vlo, vhi, accp[i][j2]);
            int dlo = (h1v[i] + h2v[2 * j2])     & (D - 1);
            int dhi = (h1v[i] + h2v[2 * j2 + 1]) & (D - 1);
            atomicAdd(&outacc[dlo], vlo);
            atomicAdd(&outacc[dhi], vhi);
        }
    }

    __syncthreads();
    // ---- flush private accumulator to global output ----
    float* outb = out + (size_t)b * D;
    #pragma unroll
    for (int i = tid; i < D; i += 256) {
        float v = outacc[i];
        if (v != 0.0f) atomicAdd(&outb[i], v);
    }
}

__global__ void zero_out_kernel(float* __restrict__ out, int n)
{
    int i = blockIdx.x * blockDim.x + threadIdx.x;
    if (i < n) out[i] = 0.0f;
}

extern "C" void kernel_launch(void* const* d_in, const int* in_sizes, int n_in,
                              void* d_out, int out_size)
{
    const float* x1 = (const float*)d_in[0];   // bottom1 [32,14,14,512]
    const float* x2 = (const float*)d_in[1];   // bottom2 [32,14,14,512]
    const float* s1 = (const float*)d_in[2];   // rand_s_1 [512]
    const float* s2 = (const float*)d_in[3];   // rand_s_2 [512]
    const int*   h1 = (const int*)d_in[4];     // rand_h_1 [512]
    const int*   h2 = (const int*)d_in[5];     // rand_h_2 [512]
    float* out = (float*)d_out;                // [32, 8192] float32

    const int n = BATCH * D;
    zero_out_kernel<<<(n + 255) / 256, 256>>>(out, n);

    dim3 grid(4, 4, BATCH);   // 512 blocks
    cbp_fused<<<grid, 256>>>(x1, x2, s1, s2, h1, h2, out);
}